// round 14
// baseline (speedup 1.0000x reference)
#include <cuda_runtime.h>
#include <cstdint>

// Problem geometry
#define CB_K 512
#define CB_C 64
#define HW   4096                     // 64*64 pixels per (b,t) plane
#define N_PIX  524288
#define Q_ELEMS 33554432
#define OFF_IDX  Q_ELEMS
#define OFF_LOSS (OFF_IDX + N_PIX)
#define OFF_ENT  (OFF_LOSS + 1)

// Persistent config: 148 CTAs (1/SM), 256 threads, equal pixel split
#define THREADS 256
#define NCTAS   148
#define ESTRIDE 516                   // padded floats per channel row of codebook (smem)
#define SMEM_FLOATS (CB_C * ESTRIDE)  // 33024 floats
#define SMEM_BYTES (SMEM_FLOATS*4 + CB_K*4 /*E*/ + CB_K*4 /*hist*/ + 4*4 /*lane_sum*/)

typedef unsigned long long u64;
typedef unsigned int u32;

// Constant-bank copy of codes 0..255, transposed [c][k] (64KB = user-const limit).
__constant__ float ec[CB_C][256];
__device__ float   g_scratch[CB_C * 256];

__device__ double   g_lane[4] = {0.0, 0.0, 0.0, 0.0};
__device__ int      g_counts[CB_K] = {};
__device__ unsigned g_ticket = 0u;

// Transpose codes 0..255 of cb[k][c] into g_scratch[c][k] (bit-identical copies).
__global__ void vq_prep(const float* __restrict__ cb) {
    int c = blockIdx.x;            // 0..63
    int k = threadIdx.x;           // 0..255
    g_scratch[c * 256 + k] = cb[k * CB_C + c];
}

__global__ void __launch_bounds__(THREADS, 1)
vq_main(const float* __restrict__ x, const float* __restrict__ cb, float* __restrict__ out) {
    extern __shared__ float smem[];
    float* es   = smem;                       // codebook transposed [c][k], stride 516
    float* ee   = smem + SMEM_FLOATS;         // E_k (fp32 sequential fma, reference chain)
    int*   hist = (int*)(ee + CB_K);          // per-CTA histogram (whole CTA lifetime)
    float* lane_sum = (float*)(hist + CB_K);  // per-CTA loss partials by (index mod 4)

    const int tid = threadIdx.x;

    // ---- one-time staging per CTA ----
    for (int i = tid; i < CB_K * CB_C; i += THREADS) {
        int k = i >> 6, c = i & 63;
        es[c * ESTRIDE + k] = cb[i];
    }
    for (int k = tid; k < CB_K; k += THREADS) hist[k] = 0;
    if (tid < 4) lane_sum[tid] = 0.f;
    __syncthreads();
    for (int k = tid; k < CB_K; k += THREADS) {
        float s = 0.f;
        #pragma unroll
        for (int c = 0; c < CB_C; ++c) { float e = es[c * ESTRIDE + k]; s = __fmaf_rn(e, e, s); }
        ee[k] = s;
    }
    __syncthreads();

    unsigned sbase = (unsigned)__cvta_generic_to_shared(es);
    unsigned hbase = (unsigned)__cvta_generic_to_shared(ee);

    // ---- equal pixel-range split across 148 CTAs (even-aligned boundaries) ----
    const unsigned b = blockIdx.x;
    const unsigned pstart = 2u * ((b * 262144u) / 148u);
    const unsigned pend   = 2u * (((b + 1u) * 262144u) / 148u);

    for (unsigned p0 = pstart + 2u * (unsigned)tid; p0 < pend; p0 += 2u * THREADS) {
        const unsigned plane = p0 >> 12;
        const unsigned j0 = p0 & 4095u;
        const float* xp = x + (size_t)plane * (CB_C * HW) + j0;

        // two adjacent pixels per thread; all channels in registers (x read once)
        float2 f[CB_C];
        #pragma unroll
        for (int c = 0; c < CB_C; ++c) f[c] = *(const float2*)(xp + (size_t)c * HW);

        float Sa = 0.f, Sb = 0.f;
        #pragma unroll
        for (int c = 0; c < CB_C; ++c) {
            Sa = __fmaf_rn(f[c].x, f[c].x, Sa);
            Sb = __fmaf_rn(f[c].y, f[c].y, Sb);
        }

        float bestA = 3.4e38f, bestB = 3.4e38f;
        int biA = 0, biB = 0;

        // 64 tiles of 8 codes. Tiles 0-31 read e from __constant__ (uniform address
        // -> LDCU/UR operands -> FFMA2 banking rt=2); tiles 32-63 from smem (rt=3).
        // Every lane = identical sequential fp32 fma chain over ascending c, then the
        // reference two-rounding: t=fl(S-2D); d=fl(t+E_k); argmin ascending k, strict <.
        #pragma unroll 1
        for (int kt = 0; kt < CB_K / 8; ++kt) {
            u64 a[4] = {0,0,0,0}, bb[4] = {0,0,0,0};
            if (kt < 32) {
                const int k8 = kt * 8;
                #pragma unroll
                for (int c = 0; c < CB_C; ++c) {
                    const u64* ep = reinterpret_cast<const u64*>(&ec[c][k8]);
                    u64 e0 = ep[0], e1 = ep[1], e2 = ep[2], e3 = ep[3];
                    u64 fa, fb;
                    asm("mov.b64 %0, {%1,%1};" : "=l"(fa) : "f"(f[c].x));
                    asm("mov.b64 %0, {%1,%1};" : "=l"(fb) : "f"(f[c].y));
                    asm("fma.rn.f32x2 %0, %1, %2, %0;" : "+l"(a[0])  : "l"(fa), "l"(e0));
                    asm("fma.rn.f32x2 %0, %1, %2, %0;" : "+l"(bb[0]) : "l"(fb), "l"(e0));
                    asm("fma.rn.f32x2 %0, %1, %2, %0;" : "+l"(a[1])  : "l"(fa), "l"(e1));
                    asm("fma.rn.f32x2 %0, %1, %2, %0;" : "+l"(bb[1]) : "l"(fb), "l"(e1));
                    asm("fma.rn.f32x2 %0, %1, %2, %0;" : "+l"(a[2])  : "l"(fa), "l"(e2));
                    asm("fma.rn.f32x2 %0, %1, %2, %0;" : "+l"(bb[2]) : "l"(fb), "l"(e2));
                    asm("fma.rn.f32x2 %0, %1, %2, %0;" : "+l"(a[3])  : "l"(fa), "l"(e3));
                    asm("fma.rn.f32x2 %0, %1, %2, %0;" : "+l"(bb[3]) : "l"(fb), "l"(e3));
                }
            } else {
                unsigned ebase = sbase + (unsigned)(kt * 32);
                #pragma unroll
                for (int c = 0; c < CB_C; ++c) {
                    u64 e0, e1, e2, e3;
                    unsigned ea = ebase + (unsigned)(c * (ESTRIDE * 4));
                    asm volatile("ld.shared.v2.u64 {%0,%1}, [%2];"    : "=l"(e0), "=l"(e1) : "r"(ea));
                    asm volatile("ld.shared.v2.u64 {%0,%1}, [%2+16];" : "=l"(e2), "=l"(e3) : "r"(ea));
                    u64 fa, fb;
                    asm("mov.b64 %0, {%1,%1};" : "=l"(fa) : "f"(f[c].x));
                    asm("mov.b64 %0, {%1,%1};" : "=l"(fb) : "f"(f[c].y));
                    asm("fma.rn.f32x2 %0, %1, %2, %0;" : "+l"(a[0])  : "l"(fa), "l"(e0));
                    asm("fma.rn.f32x2 %0, %1, %2, %0;" : "+l"(bb[0]) : "l"(fb), "l"(e0));
                    asm("fma.rn.f32x2 %0, %1, %2, %0;" : "+l"(a[1])  : "l"(fa), "l"(e1));
                    asm("fma.rn.f32x2 %0, %1, %2, %0;" : "+l"(bb[1]) : "l"(fb), "l"(e1));
                    asm("fma.rn.f32x2 %0, %1, %2, %0;" : "+l"(a[2])  : "l"(fa), "l"(e2));
                    asm("fma.rn.f32x2 %0, %1, %2, %0;" : "+l"(bb[2]) : "l"(fb), "l"(e2));
                    asm("fma.rn.f32x2 %0, %1, %2, %0;" : "+l"(a[3])  : "l"(fa), "l"(e3));
                    asm("fma.rn.f32x2 %0, %1, %2, %0;" : "+l"(bb[3]) : "l"(fb), "l"(e3));
                }
            }
            u64 h[4];
            {
                unsigned ha = hbase + (unsigned)(kt * 32);
                asm volatile("ld.shared.v2.u64 {%0,%1}, [%2];"    : "=l"(h[0]), "=l"(h[1]) : "r"(ha));
                asm volatile("ld.shared.v2.u64 {%0,%1}, [%2+16];" : "=l"(h[2]), "=l"(h[3]) : "r"(ha));
            }
            #pragma unroll
            for (int q = 0; q < 4; ++q) {
                float elo = __uint_as_float((u32)h[q]);
                float ehi = __uint_as_float((u32)(h[q] >> 32));
                float Dal = __uint_as_float((u32)a[q]);
                float Dah = __uint_as_float((u32)(a[q] >> 32));
                float Dbl = __uint_as_float((u32)bb[q]);
                float Dbh = __uint_as_float((u32)(bb[q] >> 32));
                float dAl = __fadd_rn(__fmaf_rn(-2.f, Dal, Sa), elo);
                float dAh = __fadd_rn(__fmaf_rn(-2.f, Dah, Sa), ehi);
                float dBl = __fadd_rn(__fmaf_rn(-2.f, Dbl, Sb), elo);
                float dBh = __fadd_rn(__fmaf_rn(-2.f, Dbh, Sb), ehi);
                int k0 = kt * 8 + 2 * q;
                if (dAl < bestA) { bestA = dAl; biA = k0;     }
                if (dAh < bestA) { bestA = dAh; biA = k0 + 1; }
                if (dBl < bestB) { bestB = dBl; biB = k0;     }
                if (dBh < bestB) { bestB = dBh; biB = k0 + 1; }
            }
        }

        atomicAdd(&hist[biA], 1);
        atomicAdd(&hist[biB], 1);

        // ---- loss (XLA NEON-vec4 emulation, validated) + ST output ----
        const bool quant = (plane >= 2);
        float scaleQ = 1.f, invQ = 1.f;
        if (quant) {
            int lg = 31 - __clz((int)plane);   // 1..6
            int kq = 7 - lg;                    // 6..1
            scaleQ = (float)(1 << kq);
            invQ   = 1.f / (float)(1 << kq);
        }
        float acc0 = 0.f, acc1 = 0.f;
        float* outq = out + (size_t)plane * (CB_C * HW) + j0;
        #pragma unroll
        for (int c = 0; c < CB_C; ++c) {
            float qa = es[c * ESTRIDE + biA];
            float qb = es[c * ESTRIDE + biB];
            float da = __fsub_rn(qa, f[c].x);
            float db = __fsub_rn(qb, f[c].y);
            float v0 = __fmul_rn(da, da);
            float v1 = __fmul_rn(db, db);
            if (quant) {
                float m0 = __fsub_rn(__fmaf_rn(v0, scaleQ, 8388608.f), 8388608.f);
                float m1 = __fsub_rn(__fmaf_rn(v1, scaleQ, 8388608.f), 8388608.f);
                acc0 = __fmaf_rn(m0, invQ, acc0);
                acc1 = __fmaf_rn(m1, invQ, acc1);
            } else {
                acc0 = __fadd_rn(v0, acc0);
                acc1 = __fadd_rn(v1, acc1);
            }
            *(float2*)(outq + (size_t)c * HW) =
                make_float2(__fadd_rn(f[c].x, da), __fadd_rn(f[c].y, db));
        }
        *(float2*)(out + OFF_IDX + p0) = make_float2((float)biA, (float)biB);

        atomicAdd(&lane_sum[p0 & 3], acc0);
        atomicAdd(&lane_sum[(p0 & 3) + 1], acc1);
    }

    // ---- per-CTA flush ----
    __syncthreads();
    if (tid < 4) atomicAdd(&g_lane[tid], (double)lane_sum[tid]);
    for (int k = tid; k < CB_K; k += THREADS) {
        int cth = hist[k];
        if (cth) atomicAdd(&g_counts[k], cth);
    }

    // ---- last-CTA finalize + self-reset (graph-replay deterministic) ----
    __shared__ unsigned is_last;
    __threadfence();
    if (tid == 0) is_last = (atomicAdd(&g_ticket, 1u) == NCTAS - 1u) ? 1u : 0u;
    __syncthreads();
    if (is_last) {
        __threadfence();
        double e = 0.0;
        for (int k = tid; k < CB_K; k += THREADS) {
            int c = g_counts[k];
            if (c) { double p = (double)c / (double)N_PIX; e -= p * log2(p); }
            g_counts[k] = 0;
        }
        double* red = (double*)smem;   // es region dead; 16B-aligned
        red[tid] = e;
        __syncthreads();
        for (int o = THREADS / 2; o > 0; o >>= 1) {
            if (tid < o) red[tid] += red[tid + o];
            __syncthreads();
        }
        if (tid == 0) {
            out[OFF_ENT] = (float)red[0];
            // NEON faddp horizontal reduce: (s0+s1) + (s2+s3), all fp32.
            float s0 = (float)g_lane[0], s1 = (float)g_lane[1];
            float s2 = (float)g_lane[2], s3 = (float)g_lane[3];
            float hs = __fadd_rn(__fadd_rn(s0, s1), __fadd_rn(s2, s3));
            float L  = hs * (1.f / 33554432.f);
            out[OFF_LOSS] = __fadd_rn(L, 0.25f * L);
            g_lane[0] = 0.0; g_lane[1] = 0.0; g_lane[2] = 0.0; g_lane[3] = 0.0;
            g_ticket = 0u;
        }
    }
}

extern "C" void kernel_launch(void* const* d_in, const int* in_sizes, int n_in,
                              void* d_out, int out_size) {
    const float* x  = (const float*)d_in[0];
    const float* cb = (const float*)d_in[1];
    float* out = (float*)d_out;
    cudaFuncSetAttribute(vq_main, cudaFuncAttributeMaxDynamicSharedMemorySize, SMEM_BYTES);
    // Transpose codes 0..255 into scratch, then D2D copy into the constant bank.
    vq_prep<<<CB_C, 256>>>(cb);
    void* scratch_ptr = nullptr;
    cudaGetSymbolAddress(&scratch_ptr, g_scratch);
    cudaMemcpyToSymbolAsync(ec, scratch_ptr, CB_C * 256 * sizeof(float), 0,
                            cudaMemcpyDeviceToDevice, 0);
    vq_main<<<NCTAS, THREADS, SMEM_BYTES>>>(x, cb, out);
}

// round 15
// speedup vs baseline: 1.2764x; 1.2764x over previous
#include <cuda_runtime.h>
#include <cuda_fp16.h>
#include <cstdint>

typedef unsigned long long u64;
typedef unsigned int u32;
typedef unsigned short u16;

// Problem geometry
#define CB_K 512
#define CB_C 64
#define HW   4096
#define N_PIX 524288
#define Q_ELEMS 33554432
#define OFF_IDX  Q_ELEMS
#define OFF_LOSS (OFF_IDX + N_PIX)
#define OFF_ENT  (OFF_LOSS + 1)

// Persistent config: 148 CTAs (1/SM), 256 threads, 2 pixels/thread per iteration
#define THREADS 256
#define NCTAS   148

// smem byte offsets
#define SB_EH   0                    // eh[c][kp] half2 (codes 2kp,2kp+1): 64*256*4 = 65536
#define SB_EE   65536                // E_k fp32: 2048
#define SB_HIST 67584                // 512 int
#define SB_CAND 69632                // 512 threads*? -> 256 threads * 2 px * 16 u16 = 16384
#define SB_LANE 86016                // 4 f32
#define SB_EMAX 86032                // 1 int
#define SMEM_BYTES 86080

__device__ double   g_lane[4] = {0.0, 0.0, 0.0, 0.0};
__device__ int      g_counts[CB_K] = {};
__device__ unsigned g_ticket = 0u;

__device__ __forceinline__ u32 pack_h2(float lo, float hi){
    u32 h; asm("cvt.rn.f16x2.f32 %0, %1, %2;" : "=r"(h) : "f"(hi), "f"(lo));
    return h;
}
#define HFMA2(acc, a, b) asm("fma.rn.f16x2 %0, %1, %2, %0;" : "+r"(acc) : "r"(a), "r"(b))

__global__ void __launch_bounds__(THREADS, 1)
vq_main(const float* __restrict__ x, const float* __restrict__ cb, float* __restrict__ out) {
    extern __shared__ char smem[];
    u32*   eh   = (u32*)(smem + SB_EH);
    float* ee   = (float*)(smem + SB_EE);
    int*   hist = (int*)(smem + SB_HIST);
    u16*   cand = (u16*)(smem + SB_CAND);
    float* lane_sum = (float*)(smem + SB_LANE);
    int*   emax_i   = (int*)(smem + SB_EMAX);

    const int tid = threadIdx.x;

    // ---- one-time staging per CTA ----
    // fp16 codebook, transposed [c][code-pair]
    for (int i = tid; i < CB_C * 256; i += THREADS) {
        int c = i >> 8, kp = i & 255;
        float e0 = cb[(2 * kp) * CB_C + c];
        float e1 = cb[(2 * kp + 1) * CB_C + c];
        eh[c * 256 + kp] = pack_h2(e0, e1);
    }
    for (int k = tid; k < CB_K; k += THREADS) hist[k] = 0;
    if (tid < 4) lane_sum[tid] = 0.f;
    if (tid == 0) *emax_i = 0;
    // E_k exact (sequential fma ascending c — reference chain) + Emax
    __syncthreads();
    for (int k = tid; k < CB_K; k += THREADS) {
        const float4* eg = (const float4*)(cb + k * CB_C);
        float s = 0.f;
        #pragma unroll
        for (int c4 = 0; c4 < 16; ++c4) {
            float4 e = __ldg(eg + c4);
            s = __fmaf_rn(e.x, e.x, s); s = __fmaf_rn(e.y, e.y, s);
            s = __fmaf_rn(e.z, e.z, s); s = __fmaf_rn(e.w, e.w, s);
        }
        ee[k] = s;
        atomicMax(emax_i, __float_as_int(s));   // positive: int order == float order
    }
    __syncthreads();

    const float Emax = __int_as_float(*emax_i);
    unsigned ehb = (unsigned)__cvta_generic_to_shared(eh);

    // ---- equal pixel-range split across 148 CTAs (even-aligned boundaries) ----
    const unsigned b = blockIdx.x;
    const unsigned pstart = 2u * ((b * 262144u) / 148u);
    const unsigned pend   = 2u * (((b + 1u) * 262144u) / 148u);

    u16* cb0 = cand + (2 * tid) * 16;
    u16* cb1 = cb0 + 16;

    for (unsigned p0 = pstart + 2u * (unsigned)tid; p0 < pend; p0 += 2u * THREADS) {
        const unsigned plane = p0 >> 12;
        const unsigned j0 = p0 & 4095u;
        const float* xp = x + (size_t)plane * (CB_C * HW) + j0;

        // ---- pass 1: S (exact ascending-c fma chain) + fp16 pack; f fp32 not kept ----
        float Sa = 0.f, Sb = 0.f;
        u32 fh[CB_C];
        #pragma unroll
        for (int c = 0; c < CB_C; ++c) {
            float2 v = *(const float2*)(xp + (size_t)c * HW);
            Sa = __fmaf_rn(v.x, v.x, Sa);
            Sb = __fmaf_rn(v.y, v.y, Sb);
            fh[c] = pack_h2(v.x, v.y);        // lo = px0, hi = px1
        }
        // Sound fp16 window: |d'-d| <= 0.075*sqrt(S*Emax)+1e-4; threshold margin = 2x.
        const float W2a = __fmaf_rn(0.15f, __fsqrt_rn(Sa * Emax), 2e-4f);
        const float W2b = __fmaf_rn(0.15f, __fsqrt_rn(Sb * Emax), 2e-4f);

        int cnt0 = 0, cnt1 = 0;
        float m0 = 3.4e38f, m1 = 3.4e38f;

        // ---- HFMA2 screen: 64 tiles x 8 codes; 4 half2 accs per pixel per tile ----
        #pragma unroll 1
        for (int kt = 0; kt < 64; ++kt) {
            u32 aA0 = 0, aA1 = 0, aA2 = 0, aA3 = 0;
            u32 aB0 = 0, aB1 = 0, aB2 = 0, aB3 = 0;
            unsigned ea = ehb + (unsigned)(kt * 16);
            #pragma unroll
            for (int c = 0; c < CB_C; ++c) {
                u32 w0, w1, w2, w3;
                asm("ld.shared.v4.u32 {%0,%1,%2,%3}, [%4];"
                    : "=r"(w0), "=r"(w1), "=r"(w2), "=r"(w3)
                    : "r"(ea + (unsigned)(c * 1024)));
                u32 ba, bbx;
                asm("prmt.b32 %0, %1, %1, 0x1010;" : "=r"(ba)  : "r"(fh[c]));
                asm("prmt.b32 %0, %1, %1, 0x3232;" : "=r"(bbx) : "r"(fh[c]));
                HFMA2(aA0, w0, ba);  HFMA2(aB0, w0, bbx);
                HFMA2(aA1, w1, ba);  HFMA2(aB1, w1, bbx);
                HFMA2(aA2, w2, ba);  HFMA2(aB2, w2, bbx);
                HFMA2(aA3, w3, ba);  HFMA2(aB3, w3, bbx);
            }
            // distances for these 8 codes
            float4 E0 = *(const float4*)(ee + kt * 8);
            float4 E1 = *(const float4*)(ee + kt * 8 + 4);
            float Ev[8] = {E0.x, E0.y, E0.z, E0.w, E1.x, E1.y, E1.z, E1.w};
            u32 av[4] = {aA0, aA1, aA2, aA3};
            u32 bv[4] = {aB0, aB1, aB2, aB3};
            float dA[8], dB[8];
            #pragma unroll
            for (int q = 0; q < 4; ++q) {
                float2 Da = __half22float2(*reinterpret_cast<__half2*>(&av[q]));
                float2 Db = __half22float2(*reinterpret_cast<__half2*>(&bv[q]));
                dA[2*q]   = __fmaf_rn(-2.f, Da.x, Sa) + Ev[2*q];
                dA[2*q+1] = __fmaf_rn(-2.f, Da.y, Sa) + Ev[2*q+1];
                dB[2*q]   = __fmaf_rn(-2.f, Db.x, Sb) + Ev[2*q];
                dB[2*q+1] = __fmaf_rn(-2.f, Db.y, Sb) + Ev[2*q+1];
            }
            float t0 = m0, t1 = m1;
            #pragma unroll
            for (int j = 0; j < 8; ++j) { t0 = fminf(t0, dA[j]); t1 = fminf(t1, dB[j]); }
            const float thr0 = t0 + W2a, thr1 = t1 + W2b;
            #pragma unroll
            for (int j = 0; j < 8; ++j) {
                if (dA[j] <= thr0) { if (cnt0 < 16) cb0[cnt0] = (u16)(kt * 8 + j); cnt0++; }
                if (dB[j] <= thr1) { if (cnt1 < 16) cb1[cnt1] = (u16)(kt * 8 + j); cnt1++; }
            }
            m0 = t0; m1 = t1;
        }

        // ---- reload f fp32 (same gmem values) for exact verify + loss + output ----
        float2 f[CB_C];
        #pragma unroll
        for (int c = 0; c < CB_C; ++c) f[c] = *(const float2*)(xp + (size_t)c * HW);

        // ---- exact verification (reference two-rounding chain), ascending k ----
        float bd0 = 3.4e38f, bd1 = 3.4e38f;
        int bk0 = 0, bk1 = 0;
        {
            int n0 = (cnt0 <= 16) ? cnt0 : CB_K;
            #pragma unroll 1
            for (int i = 0; i < n0; ++i) {
                int k = (cnt0 <= 16) ? (int)cb0[i] : i;
                const float4* eg = (const float4*)(cb + k * CB_C);
                float D = 0.f;
                #pragma unroll
                for (int c4 = 0; c4 < 16; ++c4) {
                    float4 e = __ldg(eg + c4);
                    D = __fmaf_rn(f[4*c4+0].x, e.x, D);
                    D = __fmaf_rn(f[4*c4+1].x, e.y, D);
                    D = __fmaf_rn(f[4*c4+2].x, e.z, D);
                    D = __fmaf_rn(f[4*c4+3].x, e.w, D);
                }
                float d = __fadd_rn(__fmaf_rn(-2.f, D, Sa), ee[k]);
                if (d < bd0) { bd0 = d; bk0 = k; }
            }
            int n1 = (cnt1 <= 16) ? cnt1 : CB_K;
            #pragma unroll 1
            for (int i = 0; i < n1; ++i) {
                int k = (cnt1 <= 16) ? (int)cb1[i] : i;
                const float4* eg = (const float4*)(cb + k * CB_C);
                float D = 0.f;
                #pragma unroll
                for (int c4 = 0; c4 < 16; ++c4) {
                    float4 e = __ldg(eg + c4);
                    D = __fmaf_rn(f[4*c4+0].y, e.x, D);
                    D = __fmaf_rn(f[4*c4+1].y, e.y, D);
                    D = __fmaf_rn(f[4*c4+2].y, e.z, D);
                    D = __fmaf_rn(f[4*c4+3].y, e.w, D);
                }
                float d = __fadd_rn(__fmaf_rn(-2.f, D, Sb), ee[k]);
                if (d < bd1) { bd1 = d; bk1 = k; }
            }
        }

        atomicAdd(&hist[bk0], 1);
        atomicAdd(&hist[bk1], 1);
        *(float2*)(out + OFF_IDX + p0) = make_float2((float)bk0, (float)bk1);

        // ---- loss (XLA NEON-vec4 emulation, validated) + ST output ----
        const bool quant = (plane >= 2);
        float scaleQ = 1.f, invQ = 1.f;
        if (quant) {
            int lg = 31 - __clz((int)plane);   // 1..6
            int kq = 7 - lg;                    // 6..1
            scaleQ = (float)(1 << kq);
            invQ   = 1.f / (float)(1 << kq);
        }
        float acc0 = 0.f, acc1 = 0.f;
        float* outq = out + (size_t)plane * (CB_C * HW) + j0;
        const float4* q0r = (const float4*)(cb + bk0 * CB_C);
        const float4* q1r = (const float4*)(cb + bk1 * CB_C);
        #pragma unroll
        for (int c4 = 0; c4 < 16; ++c4) {
            float4 qa4 = __ldg(q0r + c4);
            float4 qb4 = __ldg(q1r + c4);
            float qa[4] = {qa4.x, qa4.y, qa4.z, qa4.w};
            float qb[4] = {qb4.x, qb4.y, qb4.z, qb4.w};
            #pragma unroll
            for (int u = 0; u < 4; ++u) {
                int c = 4 * c4 + u;
                float da = __fsub_rn(qa[u], f[c].x);
                float db = __fsub_rn(qb[u], f[c].y);
                float v0 = __fmul_rn(da, da);
                float v1 = __fmul_rn(db, db);
                if (quant) {
                    float mq0 = __fsub_rn(__fmaf_rn(v0, scaleQ, 8388608.f), 8388608.f);
                    float mq1 = __fsub_rn(__fmaf_rn(v1, scaleQ, 8388608.f), 8388608.f);
                    acc0 = __fmaf_rn(mq0, invQ, acc0);
                    acc1 = __fmaf_rn(mq1, invQ, acc1);
                } else {
                    acc0 = __fadd_rn(v0, acc0);
                    acc1 = __fadd_rn(v1, acc1);
                }
                *(float2*)(outq + (size_t)c * HW) =
                    make_float2(__fadd_rn(f[c].x, da), __fadd_rn(f[c].y, db));
            }
        }
        // shared fp32 atomics: quantized values are multiples of 2^-6, CTA-lane
        // totals bounded -> exact; planes 0-1 within existing noise budget.
        atomicAdd(&lane_sum[p0 & 3], acc0);
        atomicAdd(&lane_sum[(p0 & 3) + 1], acc1);
    }

    // ---- per-CTA flush ----
    __syncthreads();
    if (tid < 4) atomicAdd(&g_lane[tid], (double)lane_sum[tid]);
    for (int k = tid; k < CB_K; k += THREADS) {
        int cth = hist[k];
        if (cth) atomicAdd(&g_counts[k], cth);
    }

    // ---- last-CTA finalize + self-reset (graph-replay deterministic) ----
    __shared__ unsigned is_last;
    __threadfence();
    if (tid == 0) is_last = (atomicAdd(&g_ticket, 1u) == NCTAS - 1u) ? 1u : 0u;
    __syncthreads();
    if (is_last) {
        __threadfence();
        double e = 0.0;
        for (int k = tid; k < CB_K; k += THREADS) {
            int c = g_counts[k];
            if (c) { double p = (double)c / (double)N_PIX; e -= p * log2(p); }
            g_counts[k] = 0;
        }
        double* red = (double*)smem;   // staging regions dead; 16B-aligned
        red[tid] = e;
        __syncthreads();
        for (int o = THREADS / 2; o > 0; o >>= 1) {
            if (tid < o) red[tid] += red[tid + o];
            __syncthreads();
        }
        if (tid == 0) {
            out[OFF_ENT] = (float)red[0];
            // NEON faddp horizontal reduce: (s0+s1) + (s2+s3), all fp32.
            float s0 = (float)g_lane[0], s1 = (float)g_lane[1];
            float s2 = (float)g_lane[2], s3 = (float)g_lane[3];
            float hs = __fadd_rn(__fadd_rn(s0, s1), __fadd_rn(s2, s3));
            float L  = hs * (1.f / 33554432.f);
            out[OFF_LOSS] = __fadd_rn(L, 0.25f * L);
            g_lane[0] = 0.0; g_lane[1] = 0.0; g_lane[2] = 0.0; g_lane[3] = 0.0;
            g_ticket = 0u;
        }
    }
}

extern "C" void kernel_launch(void* const* d_in, const int* in_sizes, int n_in,
                              void* d_out, int out_size) {
    const float* x  = (const float*)d_in[0];
    const float* cb = (const float*)d_in[1];
    float* out = (float*)d_out;
    cudaFuncSetAttribute(vq_main, cudaFuncAttributeMaxDynamicSharedMemorySize, SMEM_BYTES);
    vq_main<<<NCTAS, THREADS, SMEM_BYTES>>>(x, cb, out);
}

// round 16
// speedup vs baseline: 7.2262x; 5.6613x over previous
#include <cuda_runtime.h>
#include <cstdint>

// Problem geometry
#define CB_K 512
#define CB_C 64
#define HW   4096                     // 64*64 pixels per (b,t) plane
#define N_PIX  524288
#define Q_ELEMS 33554432
#define OFF_IDX  Q_ELEMS
#define OFF_LOSS (OFF_IDX + N_PIX)
#define OFF_ENT  (OFF_LOSS + 1)

// Persistent config: 148 CTAs (1/SM), 256 threads, equal pixel split
#define THREADS 256
#define NCTAS   148
#define ESTRIDE 516                   // padded floats per channel row of codebook
#define SMEM_FLOATS (CB_C * ESTRIDE)  // 33024 floats
#define SMEM_BYTES (SMEM_FLOATS*4 + CB_K*4 /*E*/ + CB_K*4 /*hist*/ + 4*4 /*lane_sum*/)

typedef unsigned long long u64;

__device__ double   g_lane[4] = {0.0, 0.0, 0.0, 0.0};
__device__ int      g_counts[CB_K] = {};
__device__ unsigned g_ticket = 0u;

__global__ void __launch_bounds__(THREADS, 1)
vq_main(const float* __restrict__ x, const float* __restrict__ cb, float* __restrict__ out) {
    extern __shared__ float smem[];
    float* es   = smem;                       // codebook transposed [c][k], stride 516
    float* ee   = smem + SMEM_FLOATS;         // E_k (fp32 sequential fma, reference chain)
    int*   hist = (int*)(ee + CB_K);          // per-CTA histogram (whole CTA lifetime)
    float* lane_sum = (float*)(hist + CB_K);  // per-CTA loss partials by (index mod 4)

    const int tid = threadIdx.x;

    // ---- one-time staging per CTA (persistent: amortized over ~7 tiles) ----
    for (int i = tid; i < CB_K * CB_C; i += THREADS) {
        int k = i >> 6, c = i & 63;
        es[c * ESTRIDE + k] = cb[i];
    }
    for (int k = tid; k < CB_K; k += THREADS) hist[k] = 0;
    if (tid < 4) lane_sum[tid] = 0.f;
    __syncthreads();
    for (int k = tid; k < CB_K; k += THREADS) {
        float s = 0.f;
        #pragma unroll
        for (int c = 0; c < CB_C; ++c) { float e = es[c * ESTRIDE + k]; s = __fmaf_rn(e, e, s); }
        ee[k] = s;
    }
    __syncthreads();

    unsigned sbase = (unsigned)__cvta_generic_to_shared(es);
    unsigned hbase = (unsigned)__cvta_generic_to_shared(ee);

    // ---- equal pixel-range split across 148 CTAs (even-aligned boundaries) ----
    const unsigned b = blockIdx.x;
    const unsigned pstart = 2u * ((b * 262144u) / 148u);
    const unsigned pend   = 2u * (((b + 1u) * 262144u) / 148u);

    for (unsigned p0 = pstart + 2u * (unsigned)tid; p0 < pend; p0 += 2u * THREADS) {
        const unsigned plane = p0 >> 12;
        const unsigned j0 = p0 & 4095u;
        const float* xp = x + (size_t)plane * (CB_C * HW) + j0;

        // two adjacent pixels per thread; all channels in registers (x read once)
        float2 f[CB_C];
        #pragma unroll
        for (int c = 0; c < CB_C; ++c) f[c] = *(const float2*)(xp + (size_t)c * HW);

        float Sa = 0.f, Sb = 0.f;
        #pragma unroll
        for (int c = 0; c < CB_C; ++c) {
            Sa = __fmaf_rn(f[c].x, f[c].x, Sa);
            Sb = __fmaf_rn(f[c].y, f[c].y, Sb);
        }

        float bestA = 3.4e38f, bestB = 3.4e38f;
        int biA = 0, biB = 0;

        // 64 tiles of 8 codes: packed-FFMA2 sequential-fma dot, then the reference
        // two-rounding chain: t = fl(S - 2D); d = fl(t + E_k); argmin ascending k.
        #pragma unroll 1
        for (int kt = 0; kt < CB_K / 8; ++kt) {
            u64 a[4] = {0,0,0,0}, bb[4] = {0,0,0,0};
            unsigned ebase = sbase + (unsigned)(kt * 32);
            #pragma unroll
            for (int c = 0; c < CB_C; ++c) {
                u64 e0, e1, e2, e3;
                unsigned ea = ebase + (unsigned)(c * (ESTRIDE * 4));
                asm volatile("ld.shared.v2.u64 {%0,%1}, [%2];"    : "=l"(e0), "=l"(e1) : "r"(ea));
                asm volatile("ld.shared.v2.u64 {%0,%1}, [%2+16];" : "=l"(e2), "=l"(e3) : "r"(ea));
                u64 fa, fb;
                asm("mov.b64 %0, {%1,%1};" : "=l"(fa) : "f"(f[c].x));
                asm("mov.b64 %0, {%1,%1};" : "=l"(fb) : "f"(f[c].y));
                asm("fma.rn.f32x2 %0, %1, %2, %0;" : "+l"(a[0])  : "l"(fa), "l"(e0));
                asm("fma.rn.f32x2 %0, %1, %2, %0;" : "+l"(a[1])  : "l"(fa), "l"(e1));
                asm("fma.rn.f32x2 %0, %1, %2, %0;" : "+l"(a[2])  : "l"(fa), "l"(e2));
                asm("fma.rn.f32x2 %0, %1, %2, %0;" : "+l"(a[3])  : "l"(fa), "l"(e3));
                asm("fma.rn.f32x2 %0, %1, %2, %0;" : "+l"(bb[0]) : "l"(fb), "l"(e0));
                asm("fma.rn.f32x2 %0, %1, %2, %0;" : "+l"(bb[1]) : "l"(fb), "l"(e1));
                asm("fma.rn.f32x2 %0, %1, %2, %0;" : "+l"(bb[2]) : "l"(fb), "l"(e2));
                asm("fma.rn.f32x2 %0, %1, %2, %0;" : "+l"(bb[3]) : "l"(fb), "l"(e3));
            }
            u64 h[4];
            {
                unsigned ha = hbase + (unsigned)(kt * 32);
                asm volatile("ld.shared.v2.u64 {%0,%1}, [%2];"    : "=l"(h[0]), "=l"(h[1]) : "r"(ha));
                asm volatile("ld.shared.v2.u64 {%0,%1}, [%2+16];" : "=l"(h[2]), "=l"(h[3]) : "r"(ha));
            }
            #pragma unroll
            for (int q = 0; q < 4; ++q) {
                float elo = __uint_as_float((unsigned)h[q]);
                float ehi = __uint_as_float((unsigned)(h[q] >> 32));
                float Dal = __uint_as_float((unsigned)a[q]);
                float Dah = __uint_as_float((unsigned)(a[q] >> 32));
                float Dbl = __uint_as_float((unsigned)bb[q]);
                float Dbh = __uint_as_float((unsigned)(bb[q] >> 32));
                float dAl = __fadd_rn(__fmaf_rn(-2.f, Dal, Sa), elo);
                float dAh = __fadd_rn(__fmaf_rn(-2.f, Dah, Sa), ehi);
                float dBl = __fadd_rn(__fmaf_rn(-2.f, Dbl, Sb), elo);
                float dBh = __fadd_rn(__fmaf_rn(-2.f, Dbh, Sb), ehi);
                int k0 = kt * 8 + 2 * q;
                if (dAl < bestA) { bestA = dAl; biA = k0;     }
                if (dAh < bestA) { bestA = dAh; biA = k0 + 1; }
                if (dBl < bestB) { bestB = dBl; biB = k0;     }
                if (dBh < bestB) { bestB = dBh; biB = k0 + 1; }
            }
        }

        atomicAdd(&hist[biA], 1);
        atomicAdd(&hist[biB], 1);

        // ---- loss (XLA NEON-vec4 emulation, validated) + ST output ----
        const bool quant = (plane >= 2);
        float scaleQ = 1.f, invQ = 1.f;
        if (quant) {
            int lg = 31 - __clz((int)plane);   // 1..6
            int kq = 7 - lg;                    // 6..1
            scaleQ = (float)(1 << kq);
            invQ   = 1.f / (float)(1 << kq);
        }
        float acc0 = 0.f, acc1 = 0.f;
        float* outq = out + (size_t)plane * (CB_C * HW) + j0;
        #pragma unroll
        for (int c = 0; c < CB_C; ++c) {
            float qa = es[c * ESTRIDE + biA];
            float qb = es[c * ESTRIDE + biB];
            float da = __fsub_rn(qa, f[c].x);
            float db = __fsub_rn(qb, f[c].y);
            float v0 = __fmul_rn(da, da);
            float v1 = __fmul_rn(db, db);
            if (quant) {
                float m0 = __fsub_rn(__fmaf_rn(v0, scaleQ, 8388608.f), 8388608.f);
                float m1 = __fsub_rn(__fmaf_rn(v1, scaleQ, 8388608.f), 8388608.f);
                acc0 = __fmaf_rn(m0, invQ, acc0);
                acc1 = __fmaf_rn(m1, invQ, acc1);
            } else {
                acc0 = __fadd_rn(v0, acc0);
                acc1 = __fadd_rn(v1, acc1);
            }
            *(float2*)(outq + (size_t)c * HW) =
                make_float2(__fadd_rn(f[c].x, da), __fadd_rn(f[c].y, db));
        }
        *(float2*)(out + OFF_IDX + p0) = make_float2((float)biA, (float)biB);

        // shared fp32 atomics: quantized values are multiples of 2^-6, CTA-lane
        // totals < 2^18 -> exact; planes 0-1 within existing noise budget.
        atomicAdd(&lane_sum[p0 & 3], acc0);
        atomicAdd(&lane_sum[(p0 & 3) + 1], acc1);
    }

    // ---- per-CTA flush ----
    __syncthreads();
    if (tid < 4) atomicAdd(&g_lane[tid], (double)lane_sum[tid]);
    for (int k = tid; k < CB_K; k += THREADS) {
        int cth = hist[k];
        if (cth) atomicAdd(&g_counts[k], cth);
    }

    // ---- last-CTA finalize + self-reset (graph-replay deterministic) ----
    __shared__ unsigned is_last;
    __threadfence();
    if (tid == 0) is_last = (atomicAdd(&g_ticket, 1u) == NCTAS - 1u) ? 1u : 0u;
    __syncthreads();
    if (is_last) {
        __threadfence();
        double e = 0.0;
        for (int k = tid; k < CB_K; k += THREADS) {
            int c = g_counts[k];
            if (c) { double p = (double)c / (double)N_PIX; e -= p * log2(p); }
            g_counts[k] = 0;
        }
        double* red = (double*)smem;   // es region dead; 16B-aligned
        red[tid] = e;
        __syncthreads();
        for (int o = THREADS / 2; o > 0; o >>= 1) {
            if (tid < o) red[tid] += red[tid + o];
            __syncthreads();
        }
        if (tid == 0) {
            out[OFF_ENT] = (float)red[0];
            // NEON faddp horizontal reduce: (s0+s1) + (s2+s3), all fp32.
            float s0 = (float)g_lane[0], s1 = (float)g_lane[1];
            float s2 = (float)g_lane[2], s3 = (float)g_lane[3];
            float hs = __fadd_rn(__fadd_rn(s0, s1), __fadd_rn(s2, s3));
            float L  = hs * (1.f / 33554432.f);
            out[OFF_LOSS] = __fadd_rn(L, 0.25f * L);
            g_lane[0] = 0.0; g_lane[1] = 0.0; g_lane[2] = 0.0; g_lane[3] = 0.0;
            g_ticket = 0u;
        }
    }
}

extern "C" void kernel_launch(void* const* d_in, const int* in_sizes, int n_in,
                              void* d_out, int out_size) {
    const float* x  = (const float*)d_in[0];
    const float* cb = (const float*)d_in[1];
    float* out = (float*)d_out;
    cudaFuncSetAttribute(vq_main, cudaFuncAttributeMaxDynamicSharedMemorySize, SMEM_BYTES);
    vq_main<<<NCTAS, THREADS, SMEM_BYTES>>>(x, cb, out);
}

// round 17
// speedup vs baseline: 7.2503x; 1.0033x over previous
#include <cuda_runtime.h>
#include <cstdint>

// Problem geometry
#define CB_K 512
#define CB_C 64
#define HW   4096                     // 64*64 pixels per (b,t) plane
#define N_PIX  524288
#define Q_ELEMS 33554432
#define OFF_IDX  Q_ELEMS
#define OFF_LOSS (OFF_IDX + N_PIX)
#define OFF_ENT  (OFF_LOSS + 1)

// Persistent config: 148 CTAs (1/SM), 256 threads, equal pixel split
#define THREADS 256
#define NCTAS   148
#define ESTRIDE 516                   // padded floats per channel row of codebook
#define SMEM_FLOATS (CB_C * ESTRIDE)  // 33024 floats
#define SMEM_BYTES (SMEM_FLOATS*4 + CB_K*4 /*E*/ + CB_K*4 /*hist*/ + 4*4 /*lane_sum*/)

typedef unsigned long long u64;

__device__ double   g_lane[4] = {0.0, 0.0, 0.0, 0.0};
__device__ int      g_counts[CB_K] = {};
__device__ unsigned g_ticket = 0u;

__global__ void __launch_bounds__(THREADS, 1)
vq_main(const float* __restrict__ x, const float* __restrict__ cb, float* __restrict__ out) {
    extern __shared__ float smem[];
    float* es   = smem;                       // codebook transposed [c][k], stride 516
    float* ee   = smem + SMEM_FLOATS;         // E_k (fp32 sequential fma, reference chain)
    int*   hist = (int*)(ee + CB_K);          // per-CTA histogram (whole CTA lifetime)
    float* lane_sum = (float*)(hist + CB_K);  // per-CTA loss partials by (index mod 4)

    const int tid = threadIdx.x;

    // ---- one-time staging per CTA (persistent: amortized over ~7 tiles) ----
    for (int i = tid; i < CB_K * CB_C; i += THREADS) {
        int k = i >> 6, c = i & 63;
        es[c * ESTRIDE + k] = cb[i];
    }
    for (int k = tid; k < CB_K; k += THREADS) hist[k] = 0;
    if (tid < 4) lane_sum[tid] = 0.f;
    __syncthreads();
    for (int k = tid; k < CB_K; k += THREADS) {
        float s = 0.f;
        #pragma unroll
        for (int c = 0; c < CB_C; ++c) { float e = es[c * ESTRIDE + k]; s = __fmaf_rn(e, e, s); }
        ee[k] = s;
    }
    __syncthreads();

    unsigned sbase = (unsigned)__cvta_generic_to_shared(es);
    unsigned hbase = (unsigned)__cvta_generic_to_shared(ee);

    // ---- equal pixel-range split across 148 CTAs (even-aligned boundaries) ----
    const unsigned b = blockIdx.x;
    const unsigned pstart = 2u * ((b * 262144u) / 148u);
    const unsigned pend   = 2u * (((b + 1u) * 262144u) / 148u);

    for (unsigned p0 = pstart + 2u * (unsigned)tid; p0 < pend; p0 += 2u * THREADS) {
        const unsigned plane = p0 >> 12;
        const unsigned j0 = p0 & 4095u;
        const float* xp = x + (size_t)plane * (CB_C * HW) + j0;

        // two adjacent pixels per thread; all channels in registers (x read once)
        float2 f[CB_C];
        #pragma unroll
        for (int c = 0; c < CB_C; ++c) f[c] = *(const float2*)(xp + (size_t)c * HW);

        float Sa = 0.f, Sb = 0.f;
        #pragma unroll
        for (int c = 0; c < CB_C; ++c) {
            Sa = __fmaf_rn(f[c].x, f[c].x, Sa);
            Sb = __fmaf_rn(f[c].y, f[c].y, Sb);
        }

        float bestA = 3.4e38f, bestB = 3.4e38f;
        int biA = 0, biB = 0;

        // 64 tiles of 8 codes: packed-FFMA2 sequential-fma dot, then the reference
        // two-rounding chain: t = fl(S - 2D); d = fl(t + E_k); argmin ascending k.
        #pragma unroll 1
        for (int kt = 0; kt < CB_K / 8; ++kt) {
            u64 a[4] = {0,0,0,0}, bb[4] = {0,0,0,0};
            unsigned ebase = sbase + (unsigned)(kt * 32);
            #pragma unroll
            for (int c = 0; c < CB_C; ++c) {
                u64 e0, e1, e2, e3;
                unsigned ea = ebase + (unsigned)(c * (ESTRIDE * 4));
                asm volatile("ld.shared.v2.u64 {%0,%1}, [%2];"    : "=l"(e0), "=l"(e1) : "r"(ea));
                asm volatile("ld.shared.v2.u64 {%0,%1}, [%2+16];" : "=l"(e2), "=l"(e3) : "r"(ea));
                u64 fa, fb;
                asm("mov.b64 %0, {%1,%1};" : "=l"(fa) : "f"(f[c].x));
                asm("mov.b64 %0, {%1,%1};" : "=l"(fb) : "f"(f[c].y));
                asm("fma.rn.f32x2 %0, %1, %2, %0;" : "+l"(a[0])  : "l"(fa), "l"(e0));
                asm("fma.rn.f32x2 %0, %1, %2, %0;" : "+l"(a[1])  : "l"(fa), "l"(e1));
                asm("fma.rn.f32x2 %0, %1, %2, %0;" : "+l"(a[2])  : "l"(fa), "l"(e2));
                asm("fma.rn.f32x2 %0, %1, %2, %0;" : "+l"(a[3])  : "l"(fa), "l"(e3));
                asm("fma.rn.f32x2 %0, %1, %2, %0;" : "+l"(bb[0]) : "l"(fb), "l"(e0));
                asm("fma.rn.f32x2 %0, %1, %2, %0;" : "+l"(bb[1]) : "l"(fb), "l"(e1));
                asm("fma.rn.f32x2 %0, %1, %2, %0;" : "+l"(bb[2]) : "l"(fb), "l"(e2));
                asm("fma.rn.f32x2 %0, %1, %2, %0;" : "+l"(bb[3]) : "l"(fb), "l"(e3));
            }
            u64 h[4];
            {
                unsigned ha = hbase + (unsigned)(kt * 32);
                asm volatile("ld.shared.v2.u64 {%0,%1}, [%2];"    : "=l"(h[0]), "=l"(h[1]) : "r"(ha));
                asm volatile("ld.shared.v2.u64 {%0,%1}, [%2+16];" : "=l"(h[2]), "=l"(h[3]) : "r"(ha));
            }
            #pragma unroll
            for (int q = 0; q < 4; ++q) {
                float elo = __uint_as_float((unsigned)h[q]);
                float ehi = __uint_as_float((unsigned)(h[q] >> 32));
                float Dal = __uint_as_float((unsigned)a[q]);
                float Dah = __uint_as_float((unsigned)(a[q] >> 32));
                float Dbl = __uint_as_float((unsigned)bb[q]);
                float Dbh = __uint_as_float((unsigned)(bb[q] >> 32));
                float dAl = __fadd_rn(__fmaf_rn(-2.f, Dal, Sa), elo);
                float dAh = __fadd_rn(__fmaf_rn(-2.f, Dah, Sa), ehi);
                float dBl = __fadd_rn(__fmaf_rn(-2.f, Dbl, Sb), elo);
                float dBh = __fadd_rn(__fmaf_rn(-2.f, Dbh, Sb), ehi);
                int k0 = kt * 8 + 2 * q;
                if (dAl < bestA) { bestA = dAl; biA = k0;     }
                if (dAh < bestA) { bestA = dAh; biA = k0 + 1; }
                if (dBl < bestB) { bestB = dBl; biB = k0;     }
                if (dBh < bestB) { bestB = dBh; biB = k0 + 1; }
            }
        }

        atomicAdd(&hist[biA], 1);
        atomicAdd(&hist[biB], 1);

        // ---- loss (XLA NEON-vec4 emulation, validated) + ST output ----
        const bool quant = (plane >= 2);
        float scaleQ = 1.f, invQ = 1.f;
        if (quant) {
            int lg = 31 - __clz((int)plane);   // 1..6
            int kq = 7 - lg;                    // 6..1
            scaleQ = (float)(1 << kq);
            invQ   = 1.f / (float)(1 << kq);
        }
        float acc0 = 0.f, acc1 = 0.f;
        float* outq = out + (size_t)plane * (CB_C * HW) + j0;
        #pragma unroll
        for (int c = 0; c < CB_C; ++c) {
            float qa = es[c * ESTRIDE + biA];
            float qb = es[c * ESTRIDE + biB];
            float da = __fsub_rn(qa, f[c].x);
            float db = __fsub_rn(qb, f[c].y);
            float v0 = __fmul_rn(da, da);
            float v1 = __fmul_rn(db, db);
            if (quant) {
                float m0 = __fsub_rn(__fmaf_rn(v0, scaleQ, 8388608.f), 8388608.f);
                float m1 = __fsub_rn(__fmaf_rn(v1, scaleQ, 8388608.f), 8388608.f);
                acc0 = __fmaf_rn(m0, invQ, acc0);
                acc1 = __fmaf_rn(m1, invQ, acc1);
            } else {
                acc0 = __fadd_rn(v0, acc0);
                acc1 = __fadd_rn(v1, acc1);
            }
            *(float2*)(outq + (size_t)c * HW) =
                make_float2(__fadd_rn(f[c].x, da), __fadd_rn(f[c].y, db));
        }
        *(float2*)(out + OFF_IDX + p0) = make_float2((float)biA, (float)biB);

        // shared fp32 atomics: quantized values are multiples of 2^-6, CTA-lane
        // totals < 2^18 -> exact; planes 0-1 within existing noise budget.
        atomicAdd(&lane_sum[p0 & 3], acc0);
        atomicAdd(&lane_sum[(p0 & 3) + 1], acc1);
    }

    // ---- per-CTA flush ----
    __syncthreads();
    if (tid < 4) atomicAdd(&g_lane[tid], (double)lane_sum[tid]);
    for (int k = tid; k < CB_K; k += THREADS) {
        int cth = hist[k];
        if (cth) atomicAdd(&g_counts[k], cth);
    }

    // ---- last-CTA finalize + self-reset (graph-replay deterministic) ----
    __shared__ unsigned is_last;
    __threadfence();
    if (tid == 0) is_last = (atomicAdd(&g_ticket, 1u) == NCTAS - 1u) ? 1u : 0u;
    __syncthreads();
    if (is_last) {
        __threadfence();
        double e = 0.0;
        for (int k = tid; k < CB_K; k += THREADS) {
            int c = g_counts[k];
            if (c) { double p = (double)c / (double)N_PIX; e -= p * log2(p); }
            g_counts[k] = 0;
        }
        double* red = (double*)smem;   // es region dead; 16B-aligned
        red[tid] = e;
        __syncthreads();
        for (int o = THREADS / 2; o > 0; o >>= 1) {
            if (tid < o) red[tid] += red[tid + o];
            __syncthreads();
        }
        if (tid == 0) {
            out[OFF_ENT] = (float)red[0];
            // NEON faddp horizontal reduce: (s0+s1) + (s2+s3), all fp32.
            float s0 = (float)g_lane[0], s1 = (float)g_lane[1];
            float s2 = (float)g_lane[2], s3 = (float)g_lane[3];
            float hs = __fadd_rn(__fadd_rn(s0, s1), __fadd_rn(s2, s3));
            float L  = hs * (1.f / 33554432.f);
            out[OFF_LOSS] = __fadd_rn(L, 0.25f * L);
            g_lane[0] = 0.0; g_lane[1] = 0.0; g_lane[2] = 0.0; g_lane[3] = 0.0;
            g_ticket = 0u;
        }
    }
}

extern "C" void kernel_launch(void* const* d_in, const int* in_sizes, int n_in,
                              void* d_out, int out_size) {
    const float* x  = (const float*)d_in[0];
    const float* cb = (const float*)d_in[1];
    float* out = (float*)d_out;
    cudaFuncSetAttribute(vq_main, cudaFuncAttributeMaxDynamicSharedMemorySize, SMEM_BYTES);
    vq_main<<<NCTAS, THREADS, SMEM_BYTES>>>(x, cb, out);
}